// round 15
// baseline (speedup 1.0000x reference)
#include <cuda_runtime.h>
#include <cuda_bf16.h>

#define T 256
#define H 1024
#define E 64
#define IDIM 512
#define SI 2048
#define TOPK 6

// ---------------- device scratch ----------------
__device__ int   g_cnt[E];
__device__ int   g_slot[E * T];
__device__ int   g_tok[E * T];
__device__ float g_wt[E * T];
__device__ float g_act[T * TOPK * IDIM];   // 3 MB
__device__ float g_eo[T * TOPK * H];       // 6 MB
__device__ float g_sact[T * SI];           // 2 MB

__device__ __forceinline__ float silu(float v) { return v / (1.0f + expf(-v)); }

// ---------------- init ----------------
__global__ void init_kernel() {
    if (threadIdx.x < E) g_cnt[threadIdx.x] = 0;
}

// ---------------- gate + routing: one block per token ----------------
__global__ void gate_routing_kernel(const float* __restrict__ x,
                                    const float* __restrict__ gw,
                                    const float* __restrict__ ebias) {
    __shared__ float xs[H];
    __shared__ float part[256];
    __shared__ float logits[E];
    int t = blockIdx.x, tid = threadIdx.x;

    ((float4*)xs)[tid] = ((const float4*)(x + (size_t)t * H))[tid];
    __syncthreads();

    int e = tid >> 2, q = tid & 3;
    const float* gr = gw + (size_t)e * H + q * 256;
    const float* xr = xs + q * 256;
    float s = 0.0f;
#pragma unroll 8
    for (int k = 0; k < 256; k += 4) {
        float4 g = *(const float4*)(gr + k);
        float4 xv = *(const float4*)(xr + k);
        s += g.x * xv.x + g.y * xv.y + g.z * xv.z + g.w * xv.w;
    }
    part[tid] = s;
    __syncthreads();
    if (tid < E) logits[tid] = part[tid * 4] + part[tid * 4 + 1] + part[tid * 4 + 2] + part[tid * 4 + 3];
    __syncthreads();

    if (tid == 0) {
        float sc[E], swb[E];
        for (int i = 0; i < E; i++) {
            float l = logits[i];
            sc[i] = 1.0f / (1.0f + expf(-l));
            swb[i] = sc[i] + ebias[i];
        }
        float gs[8];
        for (int g = 0; g < 8; g++) {
            float m1 = -1e30f, m2 = -1e30f;
            for (int j = 0; j < 8; j++) {
                float v = swb[g * 8 + j];
                if (v > m1) { m2 = m1; m1 = v; }
                else if (v > m2) { m2 = v; }
            }
            gs[g] = m1 + m2;
        }
        bool gsel[8];
        for (int g = 0; g < 8; g++) gsel[g] = false;
        for (int r = 0; r < 4; r++) {
            int best = 0; float bv = -1e30f;
            for (int g = 0; g < 8; g++)
                if (!gsel[g] && gs[g] > bv) { bv = gs[g]; best = g; }
            gsel[best] = true;
        }
        bool picked[E];
        for (int i = 0; i < E; i++) picked[i] = false;
        int idx[TOPK];
        float wsum = 0.0f;
        for (int r = 0; r < TOPK; r++) {
            int best = 0; float bv = -1e30f;
            for (int i = 0; i < E; i++) {
                if (picked[i]) continue;
                float v = gsel[i >> 3] ? swb[i] : 0.0f;
                if (v > bv) { bv = v; best = i; }
            }
            picked[best] = true;
            idx[r] = best;
            wsum += sc[best];
        }
        float inv = 2.5f / (wsum + 1e-20f);
        for (int r = 0; r < TOPK; r++) {
            int ee = idx[r];
            int pos = atomicAdd(&g_cnt[ee], 1);
            g_slot[ee * T + pos] = t * TOPK + r;
            g_tok[ee * T + pos] = t;
            g_wt[ee * T + pos] = sc[ee] * inv;
        }
    }
}

// ====== unified bf16-split MMA GEMM (R13 champion + packed 8B STS) ======
// C[M=32, N=64] = A[32, KD] * B[N, KD]^T, fp32 in HBM, converted to bf16
// hi/lo in-register, 3-term MMA (hi*hi + hi*lo + lo*hi) for fp32 accuracy.
// 128 threads = 4 warps: warp (wm, wn) handles m16 x n32.
// Staging: 8 consecutive lanes cover one row's 128B (optimal coalescing);
// hi/lo planes stored via single uint2 (8B) stores — bit-identical values.

__device__ __forceinline__ void ldsm4(unsigned r[4], unsigned addr) {
    asm volatile("ldmatrix.sync.aligned.m8n8.x4.shared.b16 {%0,%1,%2,%3}, [%4];"
        : "=r"(r[0]), "=r"(r[1]), "=r"(r[2]), "=r"(r[3]) : "r"(addr));
}

__device__ __forceinline__ void mma_bf16(float c[4], const unsigned a[4],
                                         unsigned b0, unsigned b1) {
    asm("mma.sync.aligned.m16n8k16.row.col.f32.bf16.bf16.f32 "
        "{%0,%1,%2,%3}, {%4,%5,%6,%7}, {%8,%9}, {%0,%1,%2,%3};"
        : "+f"(c[0]), "+f"(c[1]), "+f"(c[2]), "+f"(c[3])
        : "r"(a[0]), "r"(a[1]), "r"(a[2]), "r"(a[3]), "r"(b0), "r"(b1));
}

// same values as champion cvt_store, stored as two 8B transactions per plane
__device__ __forceinline__ void cvt_store(float4 v, __nv_bfloat16* hi, __nv_bfloat16* lo) {
    __nv_bfloat162 h01 = __floats2bfloat162_rn(v.x, v.y);
    __nv_bfloat162 h23 = __floats2bfloat162_rn(v.z, v.w);
    float2 f01 = __bfloat1622float2(h01);
    float2 f23 = __bfloat1622float2(h23);
    __nv_bfloat162 l01 = __floats2bfloat162_rn(v.x - f01.x, v.y - f01.y);
    __nv_bfloat162 l23 = __floats2bfloat162_rn(v.z - f23.x, v.w - f23.y);
    *(uint2*)hi = make_uint2(*(unsigned*)&h01, *(unsigned*)&h23);
    *(uint2*)lo = make_uint2(*(unsigned*)&l01, *(unsigned*)&l23);
}

// smem element layout (bf16 counts):
//   sA: [2 buf][2 plane][32*40]
//   sB: [2 buf][NB][2 plane][64*40]
#define APLANE 1280
#define BPLANE 2560

// EPI: 0 = silu(acc0)*acc1   1 = acc0 * combine_weight   2 = plain acc0
template<int KD, bool TWOB, int EPI, bool GATHER, bool ATOK, int ASRC, int ODST>
__device__ __forceinline__ void gemm_body(
    int bx, int by, int bz,
    const float* __restrict__ Ain, const float* __restrict__ B1in,
    const float* __restrict__ B2in, float* __restrict__ Oout,
    int ostride, long estrideB, char* dynsmem)
{
    constexpr int NB = TWOB ? 2 : 1;
    constexpr int NCH = KD / 32;

    const float* A = (ASRC == 0) ? Ain : (ASRC == 1) ? (const float*)g_act : (const float*)g_sact;
    float* O = (ODST == 0) ? Oout : (ODST == 1) ? g_act : (ODST == 2) ? g_eo : g_sact;

    int tid = threadIdx.x, lane = tid & 31, wid = tid >> 5;
    int wm = wid & 1, wn = wid >> 1;
    int n0 = bx * 64;

    __nv_bfloat16* sA = (__nv_bfloat16*)dynsmem;
    __nv_bfloat16* sB = sA + 2 * 2 * APLANE;

    __shared__ int s_row[32];
    __shared__ int s_orow[32];
    __shared__ float s_wt[32];

    int mcnt = 32;
    const float* Bp[NB];
    if (GATHER) {
        int e = by;
        int n = g_cnt[e];
        int m0 = bz * 32;
        if (m0 >= n) return;
        mcnt = min(32, n - m0);
        if (tid < 32) {
            bool v = tid < mcnt;
            int idx = e * T + m0 + tid;
            s_row[tid]  = v ? (ATOK ? g_tok[idx] : g_slot[idx]) : -1;
            s_orow[tid] = v ? g_slot[idx] : 0;
            s_wt[tid]   = v ? g_wt[idx] : 0.0f;
        }
        Bp[0] = B1in + (size_t)e * estrideB + (size_t)n0 * KD;
        if (TWOB) Bp[1] = B2in + (size_t)e * estrideB + (size_t)n0 * KD;
    } else {
        int m0 = by * 32;
        if (tid < 32) { s_row[tid] = m0 + tid; s_orow[tid] = m0 + tid; }
        Bp[0] = B1in + (size_t)n0 * KD;
        if (TWOB) Bp[1] = B2in + (size_t)n0 * KD;
    }
    __syncthreads();

    // coalesced staging map: 8 lanes cover one row's 128B segment.
    int srow = tid >> 3, scol = tid & 7;
    long aoff0 = (long)s_row[srow];
    long aoff1 = (long)s_row[srow + 16];

    float4 pa[2];
    float4 pb[NB][4];

    auto load_chunk = [&](int kt) {
        if (!GATHER || aoff0 >= 0)
            pa[0] = *(const float4*)&A[(size_t)aoff0 * KD + kt + scol * 4];
        else
            pa[0] = make_float4(0.f, 0.f, 0.f, 0.f);
        if (!GATHER || aoff1 >= 0)
            pa[1] = *(const float4*)&A[(size_t)aoff1 * KD + kt + scol * 4];
        else
            pa[1] = make_float4(0.f, 0.f, 0.f, 0.f);
#pragma unroll
        for (int m = 0; m < NB; m++)
#pragma unroll
            for (int i = 0; i < 4; i++)
                pb[m][i] = *(const float4*)&Bp[m][(size_t)(srow + 16 * i) * KD + kt + scol * 4];
    };

    auto store_chunk_buf = [&](int buf) {
#pragma unroll
        for (int i = 0; i < 2; i++)
            cvt_store(pa[i],
                &sA[(buf * 2 + 0) * APLANE + (srow + 16 * i) * 40 + scol * 4],
                &sA[(buf * 2 + 1) * APLANE + (srow + 16 * i) * 40 + scol * 4]);
#pragma unroll
        for (int m = 0; m < NB; m++)
#pragma unroll
            for (int i = 0; i < 4; i++)
                cvt_store(pb[m][i],
                    &sB[((buf * NB + m) * 2 + 0) * BPLANE + (srow + 16 * i) * 40 + scol * 4],
                    &sB[((buf * NB + m) * 2 + 1) * BPLANE + (srow + 16 * i) * 40 + scol * 4]);
    };

    float acc[NB][4][4];
#pragma unroll
    for (int m = 0; m < NB; m++)
#pragma unroll
        for (int nt = 0; nt < 4; nt++)
#pragma unroll
            for (int j = 0; j < 4; j++) acc[m][nt][j] = 0.0f;

    unsigned aSm = (unsigned)__cvta_generic_to_shared(sA);
    unsigned bSm = (unsigned)__cvta_generic_to_shared(sB);
    int arow_off = ((wm * 16 + (lane & 15)) * 40 + ((lane >> 4) & 1) * 8) * 2;
    int brow_base = wn * 32 + (lane & 7) + ((lane & 16) >> 1);
    int bcol_off = (lane & 8);

    auto compute = [&](int buf) {
        unsigned aHi = aSm + (unsigned)(buf * 2 * APLANE * 2);
        unsigned aLo = aHi + APLANE * 2;
#pragma unroll
        for (int s = 0; s < 2; s++) {
            unsigned ah[4], al[4];
            ldsm4(ah, aHi + arow_off + s * 32);
            ldsm4(al, aLo + arow_off + s * 32);
#pragma unroll
            for (int m = 0; m < NB; m++) {
                unsigned bHi = bSm + (unsigned)(((buf * NB + m) * 2) * BPLANE * 2);
                unsigned bLo = bHi + BPLANE * 2;
                int o0 = (brow_base * 40 + s * 16 + bcol_off) * 2;
                int o1 = ((brow_base + 16) * 40 + s * 16 + bcol_off) * 2;
                unsigned bh[8], bl[8];
                ldsm4(bh, bHi + o0); ldsm4(bh + 4, bHi + o1);
                ldsm4(bl, bLo + o0); ldsm4(bl + 4, bLo + o1);
#pragma unroll
                for (int nt = 0; nt < 4; nt++) {
                    mma_bf16(acc[m][nt], ah, bh[nt * 2], bh[nt * 2 + 1]);
                    mma_bf16(acc[m][nt], ah, bl[nt * 2], bl[nt * 2 + 1]);
                    mma_bf16(acc[m][nt], al, bh[nt * 2], bh[nt * 2 + 1]);
                }
            }
        }
    };

    // champion pipeline: double-buffered smem, 1 barrier per chunk
    load_chunk(0);
    store_chunk_buf(0);
    __syncthreads();
#pragma unroll 1
    for (int ch = 0; ch < NCH; ch++) {
        if (ch + 1 < NCH) load_chunk((ch + 1) * 32);
        compute(ch & 1);
        if (ch + 1 < NCH) {
            store_chunk_buf((ch + 1) & 1);
            __syncthreads();
        }
    }

    // epilogue (champion layout)
    int g = lane >> 2, tq = lane & 3;
#pragma unroll
    for (int half = 0; half < 2; half++) {
        int m = wm * 16 + g + half * 8;
        if (m >= mcnt) continue;
        float w = (EPI == 1) ? s_wt[m] : 0.0f;
        float* op = O + (size_t)s_orow[m] * ostride + n0 + wn * 32 + 2 * tq;
#pragma unroll
        for (int nt = 0; nt < 4; nt++) {
            float v0, v1;
            if (EPI == 0) {
                v0 = silu(acc[0][nt][half * 2])     * acc[1][nt][half * 2];
                v1 = silu(acc[0][nt][half * 2 + 1]) * acc[1][nt][half * 2 + 1];
            } else if (EPI == 1) {
                v0 = acc[0][nt][half * 2] * w;
                v1 = acc[0][nt][half * 2 + 1] * w;
            } else {
                v0 = acc[0][nt][half * 2];
                v1 = acc[0][nt][half * 2 + 1];
            }
            *(float2*)&op[nt * 8] = make_float2(v0, v1);
        }
    }
}

// ---- K1: sharedUp (256 blocks) + routed stageA (4096 blocks) ----
#define K1_SHARED 256
#define K1_TOTAL (K1_SHARED + 8 * 64 * 8)
#define K1_SMEM (10240 + 40960)
__global__ __launch_bounds__(128) void k1_kernel(
    const float* __restrict__ x, const float* __restrict__ w1,
    const float* __restrict__ w3, const float* __restrict__ wsg,
    const float* __restrict__ wsu)
{
    extern __shared__ char dyn[];
    int id = blockIdx.x;
    if (id < K1_SHARED) {
        // sact = silu(x @ wsg^T) * (x @ wsu^T)
        gemm_body<1024, true, 0, false, false, 0, 3>(
            id & 31, id >> 5, 0, x, wsg, wsu, nullptr, SI, 0, dyn);
    } else {
        int rid = id - K1_SHARED;
        // act = silu(x_e @ w1^T) * (x_e @ w3^T)  [gather tokens]
        gemm_body<1024, true, 0, true, true, 0, 1>(
            rid & 7, (rid >> 3) & 63, rid >> 9, x, w1, w3, nullptr,
            IDIM, (long)IDIM * H, dyn);
    }
}

// ---- K2: sharedDown (128 blocks) + routed stageB (8192 blocks) ----
#define K2_SHARED 128
#define K2_TOTAL (K2_SHARED + 16 * 64 * 8)
#define K2_SMEM (10240 + 20480)
__global__ __launch_bounds__(128) void k2_kernel(
    const float* __restrict__ w2, const float* __restrict__ wsd,
    float* __restrict__ out)
{
    extern __shared__ char dyn[];
    int id = blockIdx.x;
    if (id < K2_SHARED) {
        // out = sact @ wsd^T
        gemm_body<2048, false, 2, false, false, 2, 0>(
            id & 15, id >> 4, 0, nullptr, wsd, wsd, out, H, 0, dyn);
    } else {
        int rid = id - K2_SHARED;
        // eo = (act_e @ w2^T) * cw  [gather slots]
        gemm_body<512, false, 1, true, false, 1, 2>(
            rid & 15, (rid >> 4) & 63, rid >> 10, nullptr, w2, w2, nullptr,
            H, (long)H * IDIM, dyn);
    }
}

// ---- combine: out += sum of the 6 weighted expert outputs per token ----
__global__ void combine_kernel(float* __restrict__ out) {
    int idx = blockIdx.x * 256 + threadIdx.x;
    int t = idx >> 10;
    int h = idx & 1023;
    float s = out[idx];
#pragma unroll
    for (int k = 0; k < TOPK; k++)
        s += g_eo[((size_t)(t * TOPK + k) << 10) + h];
    out[idx] = s;
}

// ---------------- launch ----------------
extern "C" void kernel_launch(void* const* d_in, const int* in_sizes, int n_in,
                              void* d_out, int out_size) {
    const float* x     = (const float*)d_in[0];
    const float* gw    = (const float*)d_in[1];
    const float* ebias = (const float*)d_in[2];
    const float* w1    = (const float*)d_in[3];
    const float* w3    = (const float*)d_in[4];
    const float* w2    = (const float*)d_in[5];
    const float* wsg   = (const float*)d_in[6];
    const float* wsu   = (const float*)d_in[7];
    const float* wsd   = (const float*)d_in[8];
    float* out = (float*)d_out;

    cudaFuncSetAttribute(k1_kernel, cudaFuncAttributeMaxDynamicSharedMemorySize, K1_SMEM);
    cudaFuncSetAttribute(k2_kernel, cudaFuncAttributeMaxDynamicSharedMemorySize, K2_SMEM);

    init_kernel<<<1, 64>>>();
    gate_routing_kernel<<<T, 256>>>(x, gw, ebias);
    k1_kernel<<<K1_TOTAL, 128, K1_SMEM>>>(x, w1, w3, wsg, wsu);
    k2_kernel<<<K2_TOTAL, 128, K2_SMEM>>>(w2, wsd, out);
    combine_kernel<<<(T * H) / 256, 256>>>(out);
}

// round 16
// speedup vs baseline: 1.0060x; 1.0060x over previous
#include <cuda_runtime.h>
#include <cuda_bf16.h>

#define T 256
#define H 1024
#define E 64
#define IDIM 512
#define SI 2048
#define TOPK 6

// ---------------- device scratch ----------------
__device__ int   g_cnt[E];
__device__ int   g_slot[E * T];
__device__ int   g_tok[E * T];
__device__ float g_wt[E * T];
__device__ float g_act[T * TOPK * IDIM];   // 3 MB: routed h1, then silu(h1)*h3
__device__ float g_h3[T * TOPK * IDIM];    // 3 MB: routed h3
__device__ float g_eo[T * TOPK * H];       // 6 MB: weighted expert outputs
__device__ float g_sact[T * SI];           // 2 MB: shared h1, then silu(h1)*h3
__device__ float g_h3s[T * SI];            // 2 MB: shared h3

__device__ __forceinline__ float silu(float v) { return v / (1.0f + expf(-v)); }

// ---------------- init ----------------
__global__ void init_kernel() {
    if (threadIdx.x < E) g_cnt[threadIdx.x] = 0;
}

// ---------------- gate + routing: one block per token ----------------
__global__ void gate_routing_kernel(const float* __restrict__ x,
                                    const float* __restrict__ gw,
                                    const float* __restrict__ ebias) {
    __shared__ float xs[H];
    __shared__ float part[256];
    __shared__ float logits[E];
    int t = blockIdx.x, tid = threadIdx.x;

    ((float4*)xs)[tid] = ((const float4*)(x + (size_t)t * H))[tid];
    __syncthreads();

    int e = tid >> 2, q = tid & 3;
    const float* gr = gw + (size_t)e * H + q * 256;
    const float* xr = xs + q * 256;
    float s = 0.0f;
#pragma unroll 8
    for (int k = 0; k < 256; k += 4) {
        float4 g = *(const float4*)(gr + k);
        float4 xv = *(const float4*)(xr + k);
        s += g.x * xv.x + g.y * xv.y + g.z * xv.z + g.w * xv.w;
    }
    part[tid] = s;
    __syncthreads();
    if (tid < E) logits[tid] = part[tid * 4] + part[tid * 4 + 1] + part[tid * 4 + 2] + part[tid * 4 + 3];
    __syncthreads();

    if (tid == 0) {
        float sc[E], swb[E];
        for (int i = 0; i < E; i++) {
            float l = logits[i];
            sc[i] = 1.0f / (1.0f + expf(-l));
            swb[i] = sc[i] + ebias[i];
        }
        float gs[8];
        for (int g = 0; g < 8; g++) {
            float m1 = -1e30f, m2 = -1e30f;
            for (int j = 0; j < 8; j++) {
                float v = swb[g * 8 + j];
                if (v > m1) { m2 = m1; m1 = v; }
                else if (v > m2) { m2 = v; }
            }
            gs[g] = m1 + m2;
        }
        bool gsel[8];
        for (int g = 0; g < 8; g++) gsel[g] = false;
        for (int r = 0; r < 4; r++) {
            int best = 0; float bv = -1e30f;
            for (int g = 0; g < 8; g++)
                if (!gsel[g] && gs[g] > bv) { bv = gs[g]; best = g; }
            gsel[best] = true;
        }
        bool picked[E];
        for (int i = 0; i < E; i++) picked[i] = false;
        int idx[TOPK];
        float wsum = 0.0f;
        for (int r = 0; r < TOPK; r++) {
            int best = 0; float bv = -1e30f;
            for (int i = 0; i < E; i++) {
                if (picked[i]) continue;
                float v = gsel[i >> 3] ? swb[i] : 0.0f;
                if (v > bv) { bv = v; best = i; }
            }
            picked[best] = true;
            idx[r] = best;
            wsum += sc[best];
        }
        float inv = 2.5f / (wsum + 1e-20f);
        for (int r = 0; r < TOPK; r++) {
            int ee = idx[r];
            int pos = atomicAdd(&g_cnt[ee], 1);
            g_slot[ee * T + pos] = t * TOPK + r;
            g_tok[ee * T + pos] = t;
            g_wt[ee * T + pos] = sc[ee] * inv;
        }
    }
}

// ====== unified bf16-split MMA GEMM (R13 champion, NB=1 everywhere) ======
// C[M=32, N=64] = A[32, KD] * B[N, KD]^T, fp32 in HBM, converted to bf16
// hi/lo in-register, 3-term MMA (hi*hi + hi*lo + lo*hi) for fp32 accuracy.
// 128 threads = 4 warps: warp (wm, wn) handles m16 x n32.
// Staging: 8 consecutive lanes cover one row's 128B (optimal coalescing).

__device__ __forceinline__ void ldsm4(unsigned r[4], unsigned addr) {
    asm volatile("ldmatrix.sync.aligned.m8n8.x4.shared.b16 {%0,%1,%2,%3}, [%4];"
        : "=r"(r[0]), "=r"(r[1]), "=r"(r[2]), "=r"(r[3]) : "r"(addr));
}

__device__ __forceinline__ void mma_bf16(float c[4], const unsigned a[4],
                                         unsigned b0, unsigned b1) {
    asm("mma.sync.aligned.m16n8k16.row.col.f32.bf16.bf16.f32 "
        "{%0,%1,%2,%3}, {%4,%5,%6,%7}, {%8,%9}, {%0,%1,%2,%3};"
        : "+f"(c[0]), "+f"(c[1]), "+f"(c[2]), "+f"(c[3])
        : "r"(a[0]), "r"(a[1]), "r"(a[2]), "r"(a[3]), "r"(b0), "r"(b1));
}

// champion cvt_store (R13)
__device__ __forceinline__ void cvt_store(float4 v, __nv_bfloat16* hi, __nv_bfloat16* lo) {
    __nv_bfloat162 h01 = __floats2bfloat162_rn(v.x, v.y);
    __nv_bfloat162 h23 = __floats2bfloat162_rn(v.z, v.w);
    float2 f01 = __bfloat1622float2(h01);
    float2 f23 = __bfloat1622float2(h23);
    *(__nv_bfloat162*)hi       = h01;
    *(__nv_bfloat162*)(hi + 2) = h23;
    *(__nv_bfloat162*)lo       = __floats2bfloat162_rn(v.x - f01.x, v.y - f01.y);
    *(__nv_bfloat162*)(lo + 2) = __floats2bfloat162_rn(v.z - f23.x, v.w - f23.y);
}

// smem element layout (bf16 counts): sA [2 buf][2 plane][32*40], sB [2 buf][2 plane][64*40]
#define APLANE 1280
#define BPLANE 2560

// EPI: 1 = acc * combine_weight   2 = plain acc
// ODST: 0 = Oout param, 1 = g_act, 2 = g_eo, 3 = g_sact, 4 = g_h3, 5 = g_h3s
template<int KD, int EPI, bool GATHER, bool ATOK, int ASRC, int ODST>
__device__ __forceinline__ void gemm_body(
    int bx, int by, int bz,
    const float* __restrict__ Ain, const float* __restrict__ B1in,
    float* __restrict__ Oout,
    int ostride, long estrideB, char* dynsmem)
{
    constexpr int NCH = KD / 32;

    const float* A = (ASRC == 0) ? Ain : (ASRC == 1) ? (const float*)g_act : (const float*)g_sact;
    float* O = (ODST == 0) ? Oout : (ODST == 1) ? g_act : (ODST == 2) ? g_eo :
               (ODST == 3) ? g_sact : (ODST == 4) ? g_h3 : g_h3s;

    int tid = threadIdx.x, lane = tid & 31, wid = tid >> 5;
    int wm = wid & 1, wn = wid >> 1;
    int n0 = bx * 64;

    __nv_bfloat16* sA = (__nv_bfloat16*)dynsmem;
    __nv_bfloat16* sB = sA + 2 * 2 * APLANE;

    __shared__ int s_row[32];
    __shared__ int s_orow[32];
    __shared__ float s_wt[32];

    int mcnt = 32;
    const float* Bp;
    if (GATHER) {
        int e = by;
        int n = g_cnt[e];
        int m0 = bz * 32;
        if (m0 >= n) return;
        mcnt = min(32, n - m0);
        if (tid < 32) {
            bool v = tid < mcnt;
            int idx = e * T + m0 + tid;
            s_row[tid]  = v ? (ATOK ? g_tok[idx] : g_slot[idx]) : -1;
            s_orow[tid] = v ? g_slot[idx] : 0;
            s_wt[tid]   = v ? g_wt[idx] : 0.0f;
        }
        Bp = B1in + (size_t)e * estrideB + (size_t)n0 * KD;
    } else {
        int m0 = by * 32;
        if (tid < 32) { s_row[tid] = m0 + tid; s_orow[tid] = m0 + tid; }
        Bp = B1in + (size_t)n0 * KD;
    }
    __syncthreads();

    // coalesced staging map: 8 lanes cover one row's 128B segment.
    int srow = tid >> 3, scol = tid & 7;
    long aoff0 = (long)s_row[srow];
    long aoff1 = (long)s_row[srow + 16];

    float4 pa[2];
    float4 pb[4];

    auto load_chunk = [&](int kt) {
        if (!GATHER || aoff0 >= 0)
            pa[0] = *(const float4*)&A[(size_t)aoff0 * KD + kt + scol * 4];
        else
            pa[0] = make_float4(0.f, 0.f, 0.f, 0.f);
        if (!GATHER || aoff1 >= 0)
            pa[1] = *(const float4*)&A[(size_t)aoff1 * KD + kt + scol * 4];
        else
            pa[1] = make_float4(0.f, 0.f, 0.f, 0.f);
#pragma unroll
        for (int i = 0; i < 4; i++)
            pb[i] = *(const float4*)&Bp[(size_t)(srow + 16 * i) * KD + kt + scol * 4];
    };

    auto store_chunk_buf = [&](int buf) {
#pragma unroll
        for (int i = 0; i < 2; i++)
            cvt_store(pa[i],
                &sA[(buf * 2 + 0) * APLANE + (srow + 16 * i) * 40 + scol * 4],
                &sA[(buf * 2 + 1) * APLANE + (srow + 16 * i) * 40 + scol * 4]);
#pragma unroll
        for (int i = 0; i < 4; i++)
            cvt_store(pb[i],
                &sB[(buf * 2 + 0) * BPLANE + (srow + 16 * i) * 40 + scol * 4],
                &sB[(buf * 2 + 1) * BPLANE + (srow + 16 * i) * 40 + scol * 4]);
    };

    float acc[4][4];
#pragma unroll
    for (int nt = 0; nt < 4; nt++)
#pragma unroll
        for (int j = 0; j < 4; j++) acc[nt][j] = 0.0f;

    unsigned aSm = (unsigned)__cvta_generic_to_shared(sA);
    unsigned bSm = (unsigned)__cvta_generic_to_shared(sB);
    int arow_off = ((wm * 16 + (lane & 15)) * 40 + ((lane >> 4) & 1) * 8) * 2;
    int brow_base = wn * 32 + (lane & 7) + ((lane & 16) >> 1);
    int bcol_off = (lane & 8);

    auto compute = [&](int buf) {
        unsigned aHi = aSm + (unsigned)(buf * 2 * APLANE * 2);
        unsigned aLo = aHi + APLANE * 2;
#pragma unroll
        for (int s = 0; s < 2; s++) {
            unsigned ah[4], al[4];
            ldsm4(ah, aHi + arow_off + s * 32);
            ldsm4(al, aLo + arow_off + s * 32);
            unsigned bHi = bSm + (unsigned)((buf * 2) * BPLANE * 2);
            unsigned bLo = bHi + BPLANE * 2;
            int o0 = (brow_base * 40 + s * 16 + bcol_off) * 2;
            int o1 = ((brow_base + 16) * 40 + s * 16 + bcol_off) * 2;
            unsigned bh[8], bl[8];
            ldsm4(bh, bHi + o0); ldsm4(bh + 4, bHi + o1);
            ldsm4(bl, bLo + o0); ldsm4(bl + 4, bLo + o1);
#pragma unroll
            for (int nt = 0; nt < 4; nt++) {
                mma_bf16(acc[nt], ah, bh[nt * 2], bh[nt * 2 + 1]);
                mma_bf16(acc[nt], ah, bl[nt * 2], bl[nt * 2 + 1]);
                mma_bf16(acc[nt], al, bh[nt * 2], bh[nt * 2 + 1]);
            }
        }
    };

    // champion pipeline: double-buffered smem, 1 barrier per chunk
    load_chunk(0);
    store_chunk_buf(0);
    __syncthreads();
#pragma unroll 1
    for (int ch = 0; ch < NCH; ch++) {
        if (ch + 1 < NCH) load_chunk((ch + 1) * 32);
        compute(ch & 1);
        if (ch + 1 < NCH) {
            store_chunk_buf((ch + 1) & 1);
            __syncthreads();
        }
    }

    // epilogue (champion layout)
    int g = lane >> 2, tq = lane & 3;
#pragma unroll
    for (int half = 0; half < 2; half++) {
        int m = wm * 16 + g + half * 8;
        if (m >= mcnt) continue;
        float w = (EPI == 1) ? s_wt[m] : 1.0f;
        float* op = O + (size_t)s_orow[m] * ostride + n0 + wn * 32 + 2 * tq;
#pragma unroll
        for (int nt = 0; nt < 4; nt++) {
            float v0, v1;
            if (EPI == 1) {
                v0 = acc[nt][half * 2] * w;
                v1 = acc[nt][half * 2 + 1] * w;
            } else {
                v0 = acc[nt][half * 2];
                v1 = acc[nt][half * 2 + 1];
            }
            *(float2*)&op[nt * 8] = make_float2(v0, v1);
        }
    }
}

// ---- K1: h1/h3 plain GEMMs, all NB=1 (30 KB smem -> ~7 blocks/SM) ----
// shared: 2 mats x 32 n x 8 m = 512 blocks; routed: 2 mats x 8 n x 64 e x 8 m = 8192
#define K1_SHARED 512
#define K1_TOTAL (K1_SHARED + 8192)
#define GEMM_SMEM (10240 + 20480)
__global__ __launch_bounds__(128) void k1_kernel(
    const float* __restrict__ x, const float* __restrict__ w1,
    const float* __restrict__ w3, const float* __restrict__ wsg,
    const float* __restrict__ wsu)
{
    extern __shared__ char dyn[];
    int id = blockIdx.x;
    if (id < K1_SHARED) {
        int n = id & 31, m = (id >> 5) & 7, mat = id >> 8;
        if (mat == 0)   // h1s = x @ wsg^T -> g_sact
            gemm_body<1024, 2, false, false, 0, 3>(n, m, 0, x, wsg, nullptr, SI, 0, dyn);
        else            // h3s = x @ wsu^T -> g_h3s
            gemm_body<1024, 2, false, false, 0, 5>(n, m, 0, x, wsu, nullptr, SI, 0, dyn);
    } else {
        int rid = id - K1_SHARED;
        int n = rid & 7, e = (rid >> 3) & 63, mz = (rid >> 9) & 7, mat = rid >> 12;
        if (mat == 0)   // h1 = x_e @ w1^T -> g_act (gather tokens)
            gemm_body<1024, 2, true, true, 0, 1>(n, e, mz, x, w1, nullptr,
                                                 IDIM, (long)IDIM * H, dyn);
        else            // h3 = x_e @ w3^T -> g_h3
            gemm_body<1024, 2, true, true, 0, 4>(n, e, mz, x, w3, nullptr,
                                                 IDIM, (long)IDIM * H, dyn);
    }
}

// ---- silu-mul: act = silu(h1) * h3, in place, both routed and shared ----
#define NR4 (T * TOPK * IDIM / 4)    // 196608 float4s
#define NS4 (T * SI / 4)             // 131072 float4s
__global__ void silu_mul_kernel() {
    int idx = blockIdx.x * 256 + threadIdx.x;
    if (idx < NR4) {
        float4 a = ((const float4*)g_act)[idx];
        float4 b = ((const float4*)g_h3)[idx];
        a.x = silu(a.x) * b.x; a.y = silu(a.y) * b.y;
        a.z = silu(a.z) * b.z; a.w = silu(a.w) * b.w;
        ((float4*)g_act)[idx] = a;
    } else {
        int j = idx - NR4;
        float4 a = ((const float4*)g_sact)[j];
        float4 b = ((const float4*)g_h3s)[j];
        a.x = silu(a.x) * b.x; a.y = silu(a.y) * b.y;
        a.z = silu(a.z) * b.z; a.w = silu(a.w) * b.w;
        ((float4*)g_sact)[j] = a;
    }
}

// ---- K2: sharedDown (128 blocks) + routed stageB (8192 blocks) ----
#define K2_SHARED 128
#define K2_TOTAL (K2_SHARED + 16 * 64 * 8)
__global__ __launch_bounds__(128) void k2_kernel(
    const float* __restrict__ w2, const float* __restrict__ wsd,
    float* __restrict__ out)
{
    extern __shared__ char dyn[];
    int id = blockIdx.x;
    if (id < K2_SHARED) {
        // out = sact @ wsd^T
        gemm_body<2048, 2, false, false, 2, 0>(
            id & 15, id >> 4, 0, nullptr, wsd, out, H, 0, dyn);
    } else {
        int rid = id - K2_SHARED;
        // eo = (act_e @ w2^T) * cw  [gather slots]
        gemm_body<512, 1, true, false, 1, 2>(
            rid & 15, (rid >> 4) & 63, rid >> 10, nullptr, w2, nullptr,
            H, (long)H * IDIM, dyn);
    }
}

// ---- combine: out += sum of the 6 weighted expert outputs per token ----
__global__ void combine_kernel(float* __restrict__ out) {
    int idx = blockIdx.x * 256 + threadIdx.x;
    int t = idx >> 10;
    int h = idx & 1023;
    float s = out[idx];
#pragma unroll
    for (int k = 0; k < TOPK; k++)
        s += g_eo[((size_t)(t * TOPK + k) << 10) + h];
    out[idx] = s;
}

// ---------------- launch ----------------
extern "C" void kernel_launch(void* const* d_in, const int* in_sizes, int n_in,
                              void* d_out, int out_size) {
    const float* x     = (const float*)d_in[0];
    const float* gw    = (const float*)d_in[1];
    const float* ebias = (const float*)d_in[2];
    const float* w1    = (const float*)d_in[3];
    const float* w3    = (const float*)d_in[4];
    const float* w2    = (const float*)d_in[5];
    const float* wsg   = (const float*)d_in[6];
    const float* wsu   = (const float*)d_in[7];
    const float* wsd   = (const float*)d_in[8];
    float* out = (float*)d_out;

    cudaFuncSetAttribute(k1_kernel, cudaFuncAttributeMaxDynamicSharedMemorySize, GEMM_SMEM);
    cudaFuncSetAttribute(k2_kernel, cudaFuncAttributeMaxDynamicSharedMemorySize, GEMM_SMEM);

    init_kernel<<<1, 64>>>();
    gate_routing_kernel<<<T, 256>>>(x, gw, ebias);
    k1_kernel<<<K1_TOTAL, 128, GEMM_SMEM>>>(x, w1, w3, wsg, wsu);
    silu_mul_kernel<<<(NR4 + NS4) / 256, 256>>>();
    k2_kernel<<<K2_TOTAL, 128, GEMM_SMEM>>>(w2, wsd, out);
    combine_kernel<<<(T * H) / 256, 256>>>(out);
}

// round 17
// speedup vs baseline: 1.1038x; 1.0972x over previous
#include <cuda_runtime.h>
#include <cuda_bf16.h>

#define T 256
#define H 1024
#define E 64
#define IDIM 512
#define SI 2048
#define TOPK 6

// ---------------- device scratch ----------------
__device__ int   g_cnt[E];
__device__ int   g_slot[E * T];
__device__ int   g_tok[E * T];
__device__ float g_wt[E * T];
__device__ float g_act[T * TOPK * IDIM];   // 3 MB
__device__ float g_eo[T * TOPK * H];       // 6 MB
__device__ float g_sact[T * SI];           // 2 MB

__device__ __forceinline__ float silu(float v) { return v / (1.0f + expf(-v)); }

// ---------------- init ----------------
__global__ void init_kernel() {
    if (threadIdx.x < E) g_cnt[threadIdx.x] = 0;
}

// ---------------- gate + routing: one block per token ----------------
__global__ void gate_routing_kernel(const float* __restrict__ x,
                                    const float* __restrict__ gw,
                                    const float* __restrict__ ebias) {
    __shared__ float xs[H];
    __shared__ float part[256];
    __shared__ float logits[E];
    int t = blockIdx.x, tid = threadIdx.x;

    ((float4*)xs)[tid] = ((const float4*)(x + (size_t)t * H))[tid];
    __syncthreads();

    int e = tid >> 2, q = tid & 3;
    const float* gr = gw + (size_t)e * H + q * 256;
    const float* xr = xs + q * 256;
    float s = 0.0f;
#pragma unroll 8
    for (int k = 0; k < 256; k += 4) {
        float4 g = *(const float4*)(gr + k);
        float4 xv = *(const float4*)(xr + k);
        s += g.x * xv.x + g.y * xv.y + g.z * xv.z + g.w * xv.w;
    }
    part[tid] = s;
    __syncthreads();
    if (tid < E) logits[tid] = part[tid * 4] + part[tid * 4 + 1] + part[tid * 4 + 2] + part[tid * 4 + 3];
    __syncthreads();

    if (tid == 0) {
        float sc[E], swb[E];
        for (int i = 0; i < E; i++) {
            float l = logits[i];
            sc[i] = 1.0f / (1.0f + expf(-l));
            swb[i] = sc[i] + ebias[i];
        }
        float gs[8];
        for (int g = 0; g < 8; g++) {
            float m1 = -1e30f, m2 = -1e30f;
            for (int j = 0; j < 8; j++) {
                float v = swb[g * 8 + j];
                if (v > m1) { m2 = m1; m1 = v; }
                else if (v > m2) { m2 = v; }
            }
            gs[g] = m1 + m2;
        }
        bool gsel[8];
        for (int g = 0; g < 8; g++) gsel[g] = false;
        for (int r = 0; r < 4; r++) {
            int best = 0; float bv = -1e30f;
            for (int g = 0; g < 8; g++)
                if (!gsel[g] && gs[g] > bv) { bv = gs[g]; best = g; }
            gsel[best] = true;
        }
        bool picked[E];
        for (int i = 0; i < E; i++) picked[i] = false;
        int idx[TOPK];
        float wsum = 0.0f;
        for (int r = 0; r < TOPK; r++) {
            int best = 0; float bv = -1e30f;
            for (int i = 0; i < E; i++) {
                if (picked[i]) continue;
                float v = gsel[i >> 3] ? swb[i] : 0.0f;
                if (v > bv) { bv = v; best = i; }
            }
            picked[best] = true;
            idx[r] = best;
            wsum += sc[best];
        }
        float inv = 2.5f / (wsum + 1e-20f);
        for (int r = 0; r < TOPK; r++) {
            int ee = idx[r];
            int pos = atomicAdd(&g_cnt[ee], 1);
            g_slot[ee * T + pos] = t * TOPK + r;
            g_tok[ee * T + pos] = t;
            g_wt[ee * T + pos] = sc[ee] * inv;
        }
    }
}

// ====== unified bf16-split MMA GEMM (R13 champion + optional single-buffer) ==
// C[M=32, N=64] = A[32, KD] * B[N, KD]^T, fp32 in HBM, converted to bf16
// hi/lo in-register, 3-term MMA (hi*hi + hi*lo + lo*hi) for fp32 accuracy.
// 128 threads = 4 warps: warp (wm, wn) handles m16 x n32.
// Staging: 8 consecutive lanes cover one row's 128B (optimal coalescing).
// DBUF=1: double-buffered smem, 1 barrier/chunk (champion; used by k2).
// DBUF=0: single-buffered smem, 2 barriers/chunk, HALF the smem -> 6 blocks/SM
//         instead of 4 for the TWOB (k1) variant. Register prefetch unchanged.

__device__ __forceinline__ void ldsm4(unsigned r[4], unsigned addr) {
    asm volatile("ldmatrix.sync.aligned.m8n8.x4.shared.b16 {%0,%1,%2,%3}, [%4];"
        : "=r"(r[0]), "=r"(r[1]), "=r"(r[2]), "=r"(r[3]) : "r"(addr));
}

__device__ __forceinline__ void mma_bf16(float c[4], const unsigned a[4],
                                         unsigned b0, unsigned b1) {
    asm("mma.sync.aligned.m16n8k16.row.col.f32.bf16.bf16.f32 "
        "{%0,%1,%2,%3}, {%4,%5,%6,%7}, {%8,%9}, {%0,%1,%2,%3};"
        : "+f"(c[0]), "+f"(c[1]), "+f"(c[2]), "+f"(c[3])
        : "r"(a[0]), "r"(a[1]), "r"(a[2]), "r"(a[3]), "r"(b0), "r"(b1));
}

__device__ __forceinline__ void cvt_store(float4 v, __nv_bfloat16* hi, __nv_bfloat16* lo) {
    __nv_bfloat162 h01 = __floats2bfloat162_rn(v.x, v.y);
    __nv_bfloat162 h23 = __floats2bfloat162_rn(v.z, v.w);
    float2 f01 = __bfloat1622float2(h01);
    float2 f23 = __bfloat1622float2(h23);
    *(__nv_bfloat162*)hi       = h01;
    *(__nv_bfloat162*)(hi + 2) = h23;
    *(__nv_bfloat162*)lo       = __floats2bfloat162_rn(v.x - f01.x, v.y - f01.y);
    *(__nv_bfloat162*)(lo + 2) = __floats2bfloat162_rn(v.z - f23.x, v.w - f23.y);
}

// smem element layout (bf16 counts):
//   sA: [NBUF][2 plane][32*40]
//   sB: [NBUF][NB][2 plane][64*40]
#define APLANE 1280
#define BPLANE 2560

// EPI: 0 = silu(acc0)*acc1   1 = acc0 * combine_weight   2 = plain acc0
template<int KD, bool TWOB, int EPI, bool GATHER, bool ATOK, int ASRC, int ODST, bool DBUF>
__device__ __forceinline__ void gemm_body(
    int bx, int by, int bz,
    const float* __restrict__ Ain, const float* __restrict__ B1in,
    const float* __restrict__ B2in, float* __restrict__ Oout,
    int ostride, long estrideB, char* dynsmem)
{
    constexpr int NB = TWOB ? 2 : 1;
    constexpr int NCH = KD / 32;
    constexpr int NBUF = DBUF ? 2 : 1;

    const float* A = (ASRC == 0) ? Ain : (ASRC == 1) ? (const float*)g_act : (const float*)g_sact;
    float* O = (ODST == 0) ? Oout : (ODST == 1) ? g_act : (ODST == 2) ? g_eo : g_sact;

    int tid = threadIdx.x, lane = tid & 31, wid = tid >> 5;
    int wm = wid & 1, wn = wid >> 1;
    int n0 = bx * 64;

    __nv_bfloat16* sA = (__nv_bfloat16*)dynsmem;
    __nv_bfloat16* sB = sA + NBUF * 2 * APLANE;

    __shared__ int s_row[32];
    __shared__ int s_orow[32];
    __shared__ float s_wt[32];

    int mcnt = 32;
    const float* Bp[NB];
    if (GATHER) {
        int e = by;
        int n = g_cnt[e];
        int m0 = bz * 32;
        if (m0 >= n) return;
        mcnt = min(32, n - m0);
        if (tid < 32) {
            bool v = tid < mcnt;
            int idx = e * T + m0 + tid;
            s_row[tid]  = v ? (ATOK ? g_tok[idx] : g_slot[idx]) : -1;
            s_orow[tid] = v ? g_slot[idx] : 0;
            s_wt[tid]   = v ? g_wt[idx] : 0.0f;
        }
        Bp[0] = B1in + (size_t)e * estrideB + (size_t)n0 * KD;
        if (TWOB) Bp[1] = B2in + (size_t)e * estrideB + (size_t)n0 * KD;
    } else {
        int m0 = by * 32;
        if (tid < 32) { s_row[tid] = m0 + tid; s_orow[tid] = m0 + tid; }
        Bp[0] = B1in + (size_t)n0 * KD;
        if (TWOB) Bp[1] = B2in + (size_t)n0 * KD;
    }
    __syncthreads();

    // coalesced staging map: 8 lanes cover one row's 128B segment.
    int srow = tid >> 3, scol = tid & 7;
    long aoff0 = (long)s_row[srow];
    long aoff1 = (long)s_row[srow + 16];

    float4 pa[2];
    float4 pb[NB][4];

    auto load_chunk = [&](int kt) {
        if (!GATHER || aoff0 >= 0)
            pa[0] = *(const float4*)&A[(size_t)aoff0 * KD + kt + scol * 4];
        else
            pa[0] = make_float4(0.f, 0.f, 0.f, 0.f);
        if (!GATHER || aoff1 >= 0)
            pa[1] = *(const float4*)&A[(size_t)aoff1 * KD + kt + scol * 4];
        else
            pa[1] = make_float4(0.f, 0.f, 0.f, 0.f);
#pragma unroll
        for (int m = 0; m < NB; m++)
#pragma unroll
            for (int i = 0; i < 4; i++)
                pb[m][i] = *(const float4*)&Bp[m][(size_t)(srow + 16 * i) * KD + kt + scol * 4];
    };

    auto store_chunk_buf = [&](int buf) {
#pragma unroll
        for (int i = 0; i < 2; i++)
            cvt_store(pa[i],
                &sA[(buf * 2 + 0) * APLANE + (srow + 16 * i) * 40 + scol * 4],
                &sA[(buf * 2 + 1) * APLANE + (srow + 16 * i) * 40 + scol * 4]);
#pragma unroll
        for (int m = 0; m < NB; m++)
#pragma unroll
            for (int i = 0; i < 4; i++)
                cvt_store(pb[m][i],
                    &sB[((buf * NB + m) * 2 + 0) * BPLANE + (srow + 16 * i) * 40 + scol * 4],
                    &sB[((buf * NB + m) * 2 + 1) * BPLANE + (srow + 16 * i) * 40 + scol * 4]);
    };

    float acc[NB][4][4];
#pragma unroll
    for (int m = 0; m < NB; m++)
#pragma unroll
        for (int nt = 0; nt < 4; nt++)
#pragma unroll
            for (int j = 0; j < 4; j++) acc[m][nt][j] = 0.0f;

    unsigned aSm = (unsigned)__cvta_generic_to_shared(sA);
    unsigned bSm = (unsigned)__cvta_generic_to_shared(sB);
    int arow_off = ((wm * 16 + (lane & 15)) * 40 + ((lane >> 4) & 1) * 8) * 2;
    int brow_base = wn * 32 + (lane & 7) + ((lane & 16) >> 1);
    int bcol_off = (lane & 8);

    auto compute = [&](int buf) {
        unsigned aHi = aSm + (unsigned)(buf * 2 * APLANE * 2);
        unsigned aLo = aHi + APLANE * 2;
#pragma unroll
        for (int s = 0; s < 2; s++) {
            unsigned ah[4], al[4];
            ldsm4(ah, aHi + arow_off + s * 32);
            ldsm4(al, aLo + arow_off + s * 32);
#pragma unroll
            for (int m = 0; m < NB; m++) {
                unsigned bHi = bSm + (unsigned)(((buf * NB + m) * 2) * BPLANE * 2);
                unsigned bLo = bHi + BPLANE * 2;
                int o0 = (brow_base * 40 + s * 16 + bcol_off) * 2;
                int o1 = ((brow_base + 16) * 40 + s * 16 + bcol_off) * 2;
                unsigned bh[8], bl[8];
                ldsm4(bh, bHi + o0); ldsm4(bh + 4, bHi + o1);
                ldsm4(bl, bLo + o0); ldsm4(bl + 4, bLo + o1);
#pragma unroll
                for (int nt = 0; nt < 4; nt++) {
                    mma_bf16(acc[m][nt], ah, bh[nt * 2], bh[nt * 2 + 1]);
                    mma_bf16(acc[m][nt], ah, bl[nt * 2], bl[nt * 2 + 1]);
                    mma_bf16(acc[m][nt], al, bh[nt * 2], bh[nt * 2 + 1]);
                }
            }
        }
    };

    if (DBUF) {
        // champion pipeline: double-buffered smem, 1 barrier per chunk
        load_chunk(0);
        store_chunk_buf(0);
        __syncthreads();
#pragma unroll 1
        for (int ch = 0; ch < NCH; ch++) {
            if (ch + 1 < NCH) load_chunk((ch + 1) * 32);
            compute(ch & 1);
            if (ch + 1 < NCH) {
                store_chunk_buf((ch + 1) & 1);
                __syncthreads();
            }
        }
    } else {
        // single-buffered: store -> sync -> compute -> sync; reg prefetch kept
        load_chunk(0);
#pragma unroll 1
        for (int ch = 0; ch < NCH; ch++) {
            store_chunk_buf(0);
            __syncthreads();
            if (ch + 1 < NCH) load_chunk((ch + 1) * 32);
            compute(0);
            if (ch + 1 < NCH) __syncthreads();
        }
    }

    // epilogue (champion layout)
    int g = lane >> 2, tq = lane & 3;
#pragma unroll
    for (int half = 0; half < 2; half++) {
        int m = wm * 16 + g + half * 8;
        if (m >= mcnt) continue;
        float w = (EPI == 1) ? s_wt[m] : 0.0f;
        float* op = O + (size_t)s_orow[m] * ostride + n0 + wn * 32 + 2 * tq;
#pragma unroll
        for (int nt = 0; nt < 4; nt++) {
            float v0, v1;
            if (EPI == 0) {
                v0 = silu(acc[0][nt][half * 2])     * acc[1][nt][half * 2];
                v1 = silu(acc[0][nt][half * 2 + 1]) * acc[1][nt][half * 2 + 1];
            } else if (EPI == 1) {
                v0 = acc[0][nt][half * 2] * w;
                v1 = acc[0][nt][half * 2 + 1] * w;
            } else {
                v0 = acc[0][nt][half * 2];
                v1 = acc[0][nt][half * 2 + 1];
            }
            *(float2*)&op[nt * 8] = make_float2(v0, v1);
        }
    }
}

// ---- K1: sharedUp (256 blocks) + routed stageA (4096 blocks), single-buffer --
#define K1_SHARED 256
#define K1_TOTAL (K1_SHARED + 8 * 64 * 8)
#define K1_SMEM (5120 + 20480)    // 1 buf: A 2*1280*2 + B 2mats*2planes*2560*2
__global__ __launch_bounds__(128) void k1_kernel(
    const float* __restrict__ x, const float* __restrict__ w1,
    const float* __restrict__ w3, const float* __restrict__ wsg,
    const float* __restrict__ wsu)
{
    extern __shared__ char dyn[];
    int id = blockIdx.x;
    if (id < K1_SHARED) {
        // sact = silu(x @ wsg^T) * (x @ wsu^T)
        gemm_body<1024, true, 0, false, false, 0, 3, false>(
            id & 31, id >> 5, 0, x, wsg, wsu, nullptr, SI, 0, dyn);
    } else {
        int rid = id - K1_SHARED;
        // act = silu(x_e @ w1^T) * (x_e @ w3^T)  [gather tokens]
        gemm_body<1024, true, 0, true, true, 0, 1, false>(
            rid & 7, (rid >> 3) & 63, rid >> 9, x, w1, w3, nullptr,
            IDIM, (long)IDIM * H, dyn);
    }
}

// ---- K2: sharedDown (128 blocks) + routed stageB (8192 blocks), champion ----
#define K2_SHARED 128
#define K2_TOTAL (K2_SHARED + 16 * 64 * 8)
#define K2_SMEM (10240 + 20480)
__global__ __launch_bounds__(128) void k2_kernel(
    const float* __restrict__ w2, const float* __restrict__ wsd,
    float* __restrict__ out)
{
    extern __shared__ char dyn[];
    int id = blockIdx.x;
    if (id < K2_SHARED) {
        // out = sact @ wsd^T
        gemm_body<2048, false, 2, false, false, 2, 0, true>(
            id & 15, id >> 4, 0, nullptr, wsd, wsd, out, H, 0, dyn);
    } else {
        int rid = id - K2_SHARED;
        // eo = (act_e @ w2^T) * cw  [gather slots]
        gemm_body<512, false, 1, true, false, 1, 2, true>(
            rid & 15, (rid >> 4) & 63, rid >> 10, nullptr, w2, w2, nullptr,
            H, (long)H * IDIM, dyn);
    }
}

// ---- combine: out += sum of the 6 weighted expert outputs per token ----
__global__ void combine_kernel(float* __restrict__ out) {
    int idx = blockIdx.x * 256 + threadIdx.x;
    int t = idx >> 10;
    int h = idx & 1023;
    float s = out[idx];
#pragma unroll
    for (int k = 0; k < TOPK; k++)
        s += g_eo[((size_t)(t * TOPK + k) << 10) + h];
    out[idx] = s;
}

// ---------------- launch ----------------
extern "C" void kernel_launch(void* const* d_in, const int* in_sizes, int n_in,
                              void* d_out, int out_size) {
    const float* x     = (const float*)d_in[0];
    const float* gw    = (const float*)d_in[1];
    const float* ebias = (const float*)d_in[2];
    const float* w1    = (const float*)d_in[3];
    const float* w3    = (const float*)d_in[4];
    const float* w2    = (const float*)d_in[5];
    const float* wsg   = (const float*)d_in[6];
    const float* wsu   = (const float*)d_in[7];
    const float* wsd   = (const float*)d_in[8];
    float* out = (float*)d_out;

    cudaFuncSetAttribute(k1_kernel, cudaFuncAttributeMaxDynamicSharedMemorySize, K1_SMEM);
    cudaFuncSetAttribute(k2_kernel, cudaFuncAttributeMaxDynamicSharedMemorySize, K2_SMEM);

    init_kernel<<<1, 64>>>();
    gate_routing_kernel<<<T, 256>>>(x, gw, ebias);
    k1_kernel<<<K1_TOTAL, 128, K1_SMEM>>>(x, w1, w3, wsg, wsu);
    k2_kernel<<<K2_TOTAL, 128, K2_SMEM>>>(w2, wsd, out);
    combine_kernel<<<(T * H) / 256, 256>>>(out);
}